// round 3
// baseline (speedup 1.0000x reference)
#include <cuda_runtime.h>
#include <cuda_bf16.h>

// Problem constants (match reference_code)
#define NB_NODE 100000
#define FT      256
#define OUT_FT  256
#define NB_REL  4
#define BATCH   8192
#define DEG     16

// Scratch: v_in[b][r][f] mean-pooled neighbor features. 8192*4*256 f32 = 32 MB.
__device__ float g_vin[BATCH * NB_REL * FT];

// ---------------------------------------------------------------------------
// Kernel 1: gather + mean over DEG neighbors.
// Block = 256 threads = 4 subgroups of 64 lanes; each subgroup handles one
// (b, r) pair; each lane owns one float4 (4 feature columns).
// ---------------------------------------------------------------------------
__global__ void __launch_bounds__(256, 8)
gather_mean_kernel(const float* __restrict__ features,
                   const int* __restrict__ nidx)
{
    const int sub  = threadIdx.x >> 6;          // 0..3
    const int lane = threadIdx.x & 63;          // float4 column 0..63
    const int pair = blockIdx.x * 4 + sub;      // 0..BATCH*NB_REL-1

    const int* idx = nidx + pair * DEG;

    float4 s = make_float4(0.f, 0.f, 0.f, 0.f);
#pragma unroll
    for (int d = 0; d < DEG; d++) {
        const int n = __ldg(&idx[d]);
        const float4 v = __ldg(((const float4*)(features + n * FT)) + lane);
        s.x += v.x; s.y += v.y; s.z += v.z; s.w += v.w;
    }
    const float inv = 1.0f / (float)DEG;
    s.x *= inv; s.y *= inv; s.z *= inv; s.w *= inv;
    ((float4*)(g_vin + pair * FT))[lane] = s;
}

// ---------------------------------------------------------------------------
// Kernel 2: per-relation GEMM + bias + PReLU, mean over relations.
//   out[b, o] = 0.25 * sum_r prelu( sum_f v_in[b,r,f] * W[r,f,o] + bias[r,o] )
// Tile: BM=32 batch rows, BN=64 out cols, KC=32. 256 threads as 16x16,
// each thread computes a 2x4 microtile. fp32 FMA throughout (precision).
// ---------------------------------------------------------------------------
#define BM 32
#define BN 64
#define KC 32

__global__ void __launch_bounds__(256, 4)
rgcn_gemm_kernel(const float* __restrict__ W,      // [NB_REL][FT][OUT_FT]
                 const float* __restrict__ bias,   // [NB_REL][OUT_FT]
                 const float* __restrict__ prelu_a,
                 float* __restrict__ out)          // [BATCH][OUT_FT]
{
    __shared__ float As[BM][KC];   // v_in tile  (rows = batch, cols = f)
    __shared__ float Bs[KC][BN];   // W tile     (rows = f, cols = o)

    const int tid = threadIdx.x;
    const int tx  = tid & 15;           // out-col group (4 cols each)
    const int ty  = tid >> 4;           // batch-row group (2 rows each)
    const int bm0 = blockIdx.x * BM;    // batch tile origin
    const int bn0 = blockIdx.y * BN;    // out-col tile origin

    // A-load mapping: one float4 per thread per KC-chunk
    const int arow  = tid >> 3;         // 0..31
    const int acol4 = tid & 7;          // 0..7  (float4 within 32 floats)
    // B-load mapping: two float4 per thread per KC-chunk
    // idx j in {tid, tid+256}: brow = idx/16, bcol4 = idx%16

    const float alpha = __ldg(prelu_a);

    float run[2][4];
#pragma unroll
    for (int i = 0; i < 2; i++)
#pragma unroll
        for (int j = 0; j < 4; j++) run[i][j] = 0.f;

    for (int r = 0; r < NB_REL; r++) {
        float acc[2][4];
#pragma unroll
        for (int i = 0; i < 2; i++)
#pragma unroll
            for (int j = 0; j < 4; j++) acc[i][j] = 0.f;

        const float* Wr = W + r * (FT * OUT_FT);

        for (int kc0 = 0; kc0 < FT; kc0 += KC) {
            // Load A tile: v_in[(bm0+arow), r, kc0 + acol4*4 .. +3]
            {
                const float4 av = __ldg((const float4*)(
                    g_vin + ((bm0 + arow) * NB_REL + r) * FT + kc0 + acol4 * 4));
                *(float4*)&As[arow][acol4 * 4] = av;
            }
            // Load B tile: W[r, kc0+brow, bn0 + bcol4*4 .. +3]
#pragma unroll
            for (int j = 0; j < 2; j++) {
                const int idx  = tid + j * 256;
                const int brow = idx >> 4;
                const int bcol4 = idx & 15;
                const float4 bv = __ldg((const float4*)(
                    Wr + (kc0 + brow) * OUT_FT + bn0 + bcol4 * 4));
                *(float4*)&Bs[brow][bcol4 * 4] = bv;
            }
            __syncthreads();

#pragma unroll
            for (int k = 0; k < KC; k++) {
                const float a0 = As[ty * 2 + 0][k];
                const float a1 = As[ty * 2 + 1][k];
                const float4 bb = *(const float4*)&Bs[k][tx * 4];
                acc[0][0] += a0 * bb.x; acc[0][1] += a0 * bb.y;
                acc[0][2] += a0 * bb.z; acc[0][3] += a0 * bb.w;
                acc[1][0] += a1 * bb.x; acc[1][1] += a1 * bb.y;
                acc[1][2] += a1 * bb.z; acc[1][3] += a1 * bb.w;
            }
            __syncthreads();
        }

        // Epilogue for relation r: bias + PReLU, accumulate into run (regs only)
#pragma unroll
        for (int j = 0; j < 4; j++) {
            const float bj = __ldg(&bias[r * OUT_FT + bn0 + tx * 4 + j]);
#pragma unroll
            for (int i = 0; i < 2; i++) {
                float h = acc[i][j] + bj;
                h = (h >= 0.f) ? h : alpha * h;
                run[i][j] += h;
            }
        }
    }

    // mean over relations, store
#pragma unroll
    for (int i = 0; i < 2; i++) {
        const int row = bm0 + ty * 2 + i;
        float4 o4;
        o4.x = run[i][0] * 0.25f;
        o4.y = run[i][1] * 0.25f;
        o4.z = run[i][2] * 0.25f;
        o4.w = run[i][3] * 0.25f;
        *(float4*)(out + row * OUT_FT + bn0 + tx * 4) = o4;
    }
}

// ---------------------------------------------------------------------------
// Launch. Inputs (metadata order): features, neighbor_idx, W, b, prelu_a,
// node_list, k. node_list/k are unused by the reference math.
// ---------------------------------------------------------------------------
extern "C" void kernel_launch(void* const* d_in, const int* in_sizes, int n_in,
                              void* d_out, int out_size)
{
    const float* features = (const float*)d_in[0];
    const int*   nidx     = (const int*)d_in[1];
    const float* W        = (const float*)d_in[2];
    const float* bias     = (const float*)d_in[3];
    const float* prelu_a  = (const float*)d_in[4];
    float* out = (float*)d_out;

    // Kernel 1: 8192 blocks x 256 threads (4 (b,r) pairs per block)
    gather_mean_kernel<<<(BATCH * NB_REL) / 4, 256>>>(features, nidx);

    // Kernel 2: grid (BATCH/BM, OUT_FT/BN) = (256, 4), 256 threads
    dim3 grid(BATCH / BM, OUT_FT / BN);
    rgcn_gemm_kernel<<<grid, 256>>>(W, bias, prelu_a, out);
}

// round 4
// speedup vs baseline: 1.3414x; 1.3414x over previous
#include <cuda_runtime.h>
#include <cuda_bf16.h>

// Problem constants (match reference_code)
#define NB_NODE 100000
#define FT      256
#define OUT_FT  256
#define NB_REL  4
#define BATCH   8192
#define DEG     16

// Scratch: v_in[b][r][f] mean-pooled neighbor features. 8192*4*256 f32 = 32 MB.
__device__ float g_vin[BATCH * NB_REL * FT];

// ---------------------------------------------------------------------------
// Kernel 1: gather + mean over DEG neighbors.
// Block = 256 threads = 4 subgroups of 64 lanes; each subgroup handles one
// (b, r) pair; each lane owns one float4 (4 feature columns).
// L2-bound (~12 TB/s LTS): already at the measured cap, keep as-is.
// ---------------------------------------------------------------------------
__global__ void __launch_bounds__(256, 8)
gather_mean_kernel(const float* __restrict__ features,
                   const int* __restrict__ nidx)
{
    const int sub  = threadIdx.x >> 6;          // 0..3
    const int lane = threadIdx.x & 63;          // float4 column 0..63
    const int pair = blockIdx.x * 4 + sub;      // 0..BATCH*NB_REL-1

    const int* idx = nidx + pair * DEG;

    float4 s = make_float4(0.f, 0.f, 0.f, 0.f);
#pragma unroll
    for (int d = 0; d < DEG; d++) {
        const int n = __ldg(&idx[d]);
        const float4 v = __ldg(((const float4*)(features + n * FT)) + lane);
        s.x += v.x; s.y += v.y; s.z += v.z; s.w += v.w;
    }
    const float inv = 1.0f / (float)DEG;
    s.x *= inv; s.y *= inv; s.z *= inv; s.w *= inv;
    ((float4*)(g_vin + pair * FT))[lane] = s;
}

// ---------------------------------------------------------------------------
// Kernel 2: per-relation GEMM + bias + PReLU, mean over relations.
//   out[b, o] = 0.25 * sum_r prelu( sum_f v_in[b,r,f] * W[r,f,o] + bias[r,o] )
//
// BM=32, BN=64, KC=32. 128 threads as 8(m-groups) x 16(n-groups),
// each thread owns a 4x4 microtile -> 16 FFMA per k-step against
// 4 broadcast LDS.32 + 1 LDS.128. As padded to stride 33 to kill the
// 2-way bank conflict on the per-warp row pair.
// Grid = 1024 blocks; launch_bounds(128,7) -> ~7 CTAs/SM = one full wave.
// ---------------------------------------------------------------------------
#define BM 32
#define BN 64
#define KC 32
#define AS_STRIDE 33

__global__ void __launch_bounds__(128, 7)
rgcn_gemm_kernel(const float* __restrict__ W,      // [NB_REL][FT][OUT_FT]
                 const float* __restrict__ bias,   // [NB_REL][OUT_FT]
                 const float* __restrict__ prelu_a,
                 float* __restrict__ out)          // [BATCH][OUT_FT]
{
    __shared__ float As[BM * AS_STRIDE];   // v_in tile, padded rows
    __shared__ float Bs[KC][BN];           // W tile

    const int tid = threadIdx.x;
    const int tx  = tid & 15;            // out-col group (4 cols each)
    const int ty  = tid >> 4;            // batch-row group (4 rows each)
    const int bm0 = blockIdx.x * BM;     // batch tile origin
    const int bn0 = blockIdx.y * BN;     // out-col tile origin

    // A-load mapping: 2 float4 per thread per chunk (32x32 floats)
    const int arow0  = tid >> 3;         // 0..15  (rows 0..15 / +16)
    const int acol4  = tid & 7;          // 0..7
    // B-load mapping: 4 float4 per thread per chunk (32x64 floats)

    const float alpha = __ldg(prelu_a);

    float run[4][4];
#pragma unroll
    for (int i = 0; i < 4; i++)
#pragma unroll
        for (int j = 0; j < 4; j++) run[i][j] = 0.f;

#pragma unroll 1
    for (int r = 0; r < NB_REL; r++) {
        float acc[4][4];
#pragma unroll
        for (int i = 0; i < 4; i++)
#pragma unroll
            for (int j = 0; j < 4; j++) acc[i][j] = 0.f;

        const float* Wr = W + r * (FT * OUT_FT);

#pragma unroll 1
        for (int kc0 = 0; kc0 < FT; kc0 += KC) {
            // Load A tile: v_in[(bm0+row), r, kc0 + acol4*4 .. +3]
#pragma unroll
            for (int j = 0; j < 2; j++) {
                const int row = arow0 + j * 16;
                const float4 av = __ldg((const float4*)(
                    g_vin + ((size_t)(bm0 + row) * NB_REL + r) * FT + kc0 + acol4 * 4));
                float* dst = &As[row * AS_STRIDE + acol4 * 4];
                dst[0] = av.x; dst[1] = av.y; dst[2] = av.z; dst[3] = av.w;
            }
            // Load B tile: W[r, kc0+brow, bn0 + bcol4*4 .. +3]
#pragma unroll
            for (int j = 0; j < 4; j++) {
                const int idx   = tid + j * 128;
                const int brow  = idx >> 4;
                const int bcol4 = idx & 15;
                const float4 bv = __ldg((const float4*)(
                    Wr + (kc0 + brow) * OUT_FT + bn0 + bcol4 * 4));
                *(float4*)&Bs[brow][bcol4 * 4] = bv;
            }
            __syncthreads();

#pragma unroll
            for (int k = 0; k < KC; k++) {
                const float4 bb = *(const float4*)&Bs[k][tx * 4];
                const float a0 = As[(ty * 4 + 0) * AS_STRIDE + k];
                const float a1 = As[(ty * 4 + 1) * AS_STRIDE + k];
                const float a2 = As[(ty * 4 + 2) * AS_STRIDE + k];
                const float a3 = As[(ty * 4 + 3) * AS_STRIDE + k];
                acc[0][0] += a0 * bb.x; acc[0][1] += a0 * bb.y;
                acc[0][2] += a0 * bb.z; acc[0][3] += a0 * bb.w;
                acc[1][0] += a1 * bb.x; acc[1][1] += a1 * bb.y;
                acc[1][2] += a1 * bb.z; acc[1][3] += a1 * bb.w;
                acc[2][0] += a2 * bb.x; acc[2][1] += a2 * bb.y;
                acc[2][2] += a2 * bb.z; acc[2][3] += a2 * bb.w;
                acc[3][0] += a3 * bb.x; acc[3][1] += a3 * bb.y;
                acc[3][2] += a3 * bb.z; acc[3][3] += a3 * bb.w;
            }
            __syncthreads();
        }

        // Epilogue for relation r: bias + PReLU, accumulate into run (regs)
        const float4 bj4 = __ldg((const float4*)(bias + r * OUT_FT + bn0 + tx * 4));
        const float bj[4] = { bj4.x, bj4.y, bj4.z, bj4.w };
#pragma unroll
        for (int i = 0; i < 4; i++)
#pragma unroll
            for (int j = 0; j < 4; j++) {
                float h = acc[i][j] + bj[j];
                h = (h >= 0.f) ? h : alpha * h;
                run[i][j] += h;
            }
    }

    // mean over relations, store
#pragma unroll
    for (int i = 0; i < 4; i++) {
        const int row = bm0 + ty * 4 + i;
        float4 o4;
        o4.x = run[i][0] * 0.25f;
        o4.y = run[i][1] * 0.25f;
        o4.z = run[i][2] * 0.25f;
        o4.w = run[i][3] * 0.25f;
        *(float4*)(out + (size_t)row * OUT_FT + bn0 + tx * 4) = o4;
    }
}

// ---------------------------------------------------------------------------
// Launch. Inputs (metadata order): features, neighbor_idx, W, b, prelu_a,
// node_list, k. node_list/k are unused by the reference math.
// ---------------------------------------------------------------------------
extern "C" void kernel_launch(void* const* d_in, const int* in_sizes, int n_in,
                              void* d_out, int out_size)
{
    const float* features = (const float*)d_in[0];
    const int*   nidx     = (const int*)d_in[1];
    const float* W        = (const float*)d_in[2];
    const float* bias     = (const float*)d_in[3];
    const float* prelu_a  = (const float*)d_in[4];
    float* out = (float*)d_out;

    // Kernel 1: 8192 blocks x 256 threads (4 (b,r) pairs per block)
    gather_mean_kernel<<<(BATCH * NB_REL) / 4, 256>>>(features, nidx);

    // Kernel 2: grid (BATCH/BM, OUT_FT/BN) = (256, 4) = 1024 blocks, 128 thr
    dim3 grid(BATCH / BM, OUT_FT / BN);
    rgcn_gemm_kernel<<<grid, 128>>>(W, bias, prelu_a, out);
}